// round 16
// baseline (speedup 1.0000x reference)
#include <cuda_runtime.h>
#include <cuda_fp16.h>
#include <stdint.h>
#include <math.h>

// NT-Xent loss, symmetric-GEMM, fp16 MMA + fp16 accumulators, 2x2 warp grid
// 64x64 warp tiles, one pair-tile (I,J) per CTA (8256 CTAs). Split-N
// software pipeline per warp: GEMM(nt0-3) -> GEMM(nt4-7) with epilogue(nt0-3)
// interleaved into the kc loop (fills HMMA issue-stall gaps) -> epilogue(4-7).
// Epilogue: Schraudolph exp2(x-150), packed fma.rn.f32x2, u32-sat cvt.

#define NTOT   16384
#define BROWS  8192
#define NPAIR  8256
#define M0F    150.0f

__device__ __align__(128) unsigned char g_Zb[(size_t)NTOT * 256];   // 4 MB fp16
__device__ float  g_lrow[NTOT];
__device__ double g_acc;
__device__ double g_pos;

__device__ __forceinline__ uint32_t smem_u32(const void* p) {
    uint32_t a;
    asm("{ .reg .u64 t; cvta.to.shared.u64 t, %1; cvt.u32.u64 %0, t; }"
        : "=r"(a) : "l"(p));
    return a;
}
__device__ __forceinline__ float2 h2f2(uint32_t h) {
    __half2 v = *reinterpret_cast<__half2*>(&h);
    return __half22float2(v);
}
__device__ __forceinline__ uint64_t pk2(float x, float y) {
    uint64_t r; asm("mov.b64 %0, {%1, %2};" : "=l"(r) : "f"(x), "f"(y));
    return r;
}
__device__ __forceinline__ void upk2(uint64_t v, float& x, float& y) {
    asm("mov.b64 {%0, %1}, %2;" : "=f"(x), "=f"(y) : "l"(v));
}
__device__ __forceinline__ uint64_t sfma2(uint64_t x, uint64_t k2, uint64_t kc) {
    uint64_t r;
    asm("fma.rn.f32x2 %0, %1, %2, %3;" : "=l"(r) : "l"(x), "l"(k2), "l"(kc));
    return r;
}
__device__ __forceinline__ float bits2e(float y) {
    return __uint_as_float(__float2uint_rn(y));   // u32-sat: neg -> 0
}

// -------------------------------------------------------------------- prep
__global__ void ntxent_prep(const float* __restrict__ zi,
                            const float* __restrict__ zj) {
    int idx = blockIdx.x * blockDim.x + threadIdx.x;
    if (idx < NTOT * 64) {
        int R = idx >> 6, c2 = idx & 63;
        float2 zv = (R < BROWS)
            ? ((const float2*)zi)[(size_t)R * 64 + c2]
            : ((const float2*)zj)[(size_t)(R - BROWS) * 64 + c2];
        const float a = 1.6986436f;    // sqrt(2*log2(e))
        __half2 h = __floats2half2_rn(zv.x * a, zv.y * a);
        uint32_t bits = *reinterpret_cast<uint32_t*>(&h);
        int blk = R >> 7, rl = R & 127;
        int c = c2 * 2, chunk = c >> 3;
        uint32_t byte = (uint32_t)blk * 32768u + (uint32_t)rl * 256u
                      + (uint32_t)(((chunk ^ (rl & 7)) << 4) + (c & 7) * 2);
        *(uint32_t*)(g_Zb + byte) = bits;
    }
    if (idx < NTOT) g_lrow[idx] = 0.f;
    if (idx == 0) { g_acc = 0.0; g_pos = 0.0; }
}

// -------------------------------------------------------------------- main
__global__ void __launch_bounds__(128, 3) ntxent_main() {
    extern __shared__ unsigned char smem[];
    const int tid = threadIdx.x, lane = tid & 31, w = tid >> 5;
    const int mw = w >> 1, ch = w & 1;           // 2x2 warp grid, 64x64 tiles
    const uint32_t sI = smem_u32(smem);          // [0, 32768)
    const uint32_t sJ = sI + 32768;              // [32768, 65536)
    float* colsum = (float*)(smem + 65536);      // 128 floats

    const int b = blockIdx.x;
    const int I = (int)(128.5 - sqrt(128.5 * 128.5 - 2.0 * (double)b));
    const int J = I + (b - (I * 128 - (I * (I - 1)) / 2));

    // ---- load both 32KB blocks ----
    #pragma unroll
    for (int i = 0; i < 16; i++)
        asm volatile("cp.async.cg.shared.global [%0], [%1], 16;"
                     :: "r"(sI + tid * 16 + i * 2048),
                        "l"(g_Zb + (size_t)I * 32768 + tid * 16 + i * 2048));
    #pragma unroll
    for (int i = 0; i < 16; i++)
        asm volatile("cp.async.cg.shared.global [%0], [%1], 16;"
                     :: "r"(sJ + tid * 16 + i * 2048),
                        "l"(g_Zb + (size_t)J * 32768 + tid * 16 + i * 2048));
    asm volatile("cp.async.commit_group;");
    colsum[tid] = 0.f;
    asm volatile("cp.async.wait_group 0;");
    __syncthreads();

    uint32_t cacc[4][8][2];
    #pragma unroll
    for (int mt = 0; mt < 4; mt++)
        #pragma unroll
        for (int nt = 0; nt < 8; nt++)
            cacc[mt][nt][0] = cacc[mt][nt][1] = 0u;

    const int rBn = lane & 7, cBk = (lane >> 3) & 1, ntSel = lane >> 4;
    const int rA = mw * 64 + (lane & 15), cbA = lane >> 4;

    const int q = lane >> 2;
    const bool diagWarp = (mw == ch);
    const bool thOwn = ((lane & 3) == (q >> 1));
    const int jsel = q & 1;
    const bool doCols = (I != J);
    const uint64_t K2P = pk2(8388608.f, 8388608.f);
    const uint64_t KCP = pk2(-193420413.f, -193420413.f);
    float rsl[4] = {0.f,0.f,0.f,0.f}, rsh[4] = {0.f,0.f,0.f,0.f};
    float pv = 0.f;

    // GEMM for one kc, n-half given by np range [np0, np0+2)
    #define GEMM_KC(kc_, np0_)                                                 \
    do {                                                                       \
        uint32_t af[4][4];                                                     \
        _Pragma("unroll")                                                      \
        for (int mt = 0; mt < 4; mt++) {                                       \
            int row = rA + mt * 16;                                            \
            uint32_t adrA = sI + row * 256                                     \
                          + ((((kc_) * 2 + cbA) ^ (row & 7)) << 4);            \
            asm volatile("ldmatrix.sync.aligned.m8n8.x4.shared.b16 "           \
                         "{%0,%1,%2,%3}, [%4];"                                \
                         : "=r"(af[mt][0]), "=r"(af[mt][1]),                   \
                           "=r"(af[mt][2]), "=r"(af[mt][3]) : "r"(adrA));      \
        }                                                                      \
        _Pragma("unroll")                                                      \
        for (int np = (np0_); np < (np0_) + 2; np++) {                         \
            int row = ch * 64 + (np * 2 + ntSel) * 8 + rBn;                    \
            uint32_t adrB = sJ + row * 256                                     \
                          + ((((kc_) * 2 + cBk) ^ (row & 7)) << 4);            \
            uint32_t b0, b1, b2, b3;                                           \
            asm volatile("ldmatrix.sync.aligned.m8n8.x4.shared.b16 "           \
                         "{%0,%1,%2,%3}, [%4];"                                \
                         : "=r"(b0), "=r"(b1), "=r"(b2), "=r"(b3) : "r"(adrB));\
            _Pragma("unroll")                                                  \
            for (int mt = 0; mt < 4; mt++) {                                   \
                asm volatile("mma.sync.aligned.m16n8k16.row.col.f16.f16.f16.f16 " \
                             "{%0,%1}, {%2,%3,%4,%5}, {%6,%7}, {%0,%1};"       \
                             : "+r"(cacc[mt][np*2][0]), "+r"(cacc[mt][np*2][1])\
                             : "r"(af[mt][0]), "r"(af[mt][1]),                 \
                               "r"(af[mt][2]), "r"(af[mt][3]), "r"(b0), "r"(b1));\
                asm volatile("mma.sync.aligned.m16n8k16.row.col.f16.f16.f16.f16 " \
                             "{%0,%1}, {%2,%3,%4,%5}, {%6,%7}, {%0,%1};"       \
                             : "+r"(cacc[mt][np*2+1][0]), "+r"(cacc[mt][np*2+1][1]) \
                             : "r"(af[mt][0]), "r"(af[mt][1]),                 \
                               "r"(af[mt][2]), "r"(af[mt][3]), "r"(b2), "r"(b3));\
            }                                                                  \
        }                                                                      \
    } while (0)

    // epilogue for one nt
    #define EPI_NT(nt_)                                                        \
    do {                                                                       \
        float cax = 0.f, cay = 0.f;                                            \
        _Pragma("unroll")                                                      \
        for (int mt = 0; mt < 4; mt++) {                                       \
            float2 v0 = h2f2(cacc[mt][nt_][0]);                                \
            float2 v1 = h2f2(cacc[mt][nt_][1]);                                \
            uint64_t y0 = sfma2(pk2(v0.x, v0.y), K2P, KCP);                    \
            uint64_t y1 = sfma2(pk2(v1.x, v1.y), K2P, KCP);                    \
            float a0, b0_, a1, b1_;                                            \
            upk2(y0, a0, b0_);                                                 \
            upk2(y1, a1, b1_);                                                 \
            float e0 = bits2e(a0), e1 = bits2e(b0_);                           \
            float e2 = bits2e(a1), e3 = bits2e(b1_);                           \
            rsl[mt] += e0 + e1;                                                \
            rsh[mt] += e2 + e3;                                                \
            cax += e0 + e2;                                                    \
            cay += e1 + e3;                                                    \
        }                                                                      \
        if (doCols) {                                                          \
            _Pragma("unroll")                                                  \
            for (int o = 4; o <= 16; o <<= 1) {                                \
                cax += __shfl_xor_sync(0xffffffffu, cax, o);                   \
                cay += __shfl_xor_sync(0xffffffffu, cay, o);                   \
            }                                                                  \
            if (lane < 4) {                                                    \
                atomicAdd(&colsum[ch * 64 + (nt_) * 8 + lane * 2], cax);       \
                atomicAdd(&colsum[ch * 64 + (nt_) * 8 + lane * 2 + 1], cay);   \
            }                                                                  \
        }                                                                      \
    } while (0)

    // half fixups: pos extract + diag mask for m-tiles mt0_..mt0_+1
    #define FIXUP_HALF(mt0_)                                                   \
    do {                                                                       \
        if (J == I + 64 && diagWarp && thOwn) {                                \
            _Pragma("unroll")                                                  \
            for (int mt = (mt0_); mt < (mt0_) + 2; mt++) {                     \
                float2 v0 = h2f2(cacc[mt][2*mt][0]);                           \
                float2 v1 = h2f2(cacc[mt][2*mt+1][1]);                         \
                pv += (jsel ? v0.y : v0.x) + (jsel ? v1.y : v1.x);             \
            }                                                                  \
        }                                                                      \
        if (I == J && diagWarp && thOwn) {                                     \
            const uint32_t mk = jsel ? 0x0000FFFFu : 0xFFFF0000u;              \
            const uint32_t sv = jsel ? 0xFC000000u : 0x0000FC00u;              \
            _Pragma("unroll")                                                  \
            for (int mt = (mt0_); mt < (mt0_) + 2; mt++) {                     \
                cacc[mt][2*mt][0]   = (cacc[mt][2*mt][0]   & mk) | sv;         \
                cacc[mt][2*mt+1][1] = (cacc[mt][2*mt+1][1] & mk) | sv;         \
            }                                                                  \
        }                                                                      \
    } while (0)

    // ---- phase 1: GEMM n-half 0 (nt 0..3) ----
    #pragma unroll
    for (int kc = 0; kc < 8; kc++) GEMM_KC(kc, 0);

    // half-0 fixups (diag cols of nt 0..3 come from m-tiles 0..1)
    FIXUP_HALF(0);

    // ---- phase 2: GEMM n-half 1, epilogue(nt 0..3) interleaved ----
    #pragma unroll
    for (int kc = 0; kc < 8; kc++) {
        GEMM_KC(kc, 2);
        if (kc & 1) EPI_NT(kc >> 1);
    }

    // half-1 fixups (diag cols of nt 4..7 come from m-tiles 2..3)
    FIXUP_HALF(2);

    // ---- phase 3: epilogue n-half 1 ----
    #pragma unroll
    for (int nt = 4; nt < 8; nt++) EPI_NT(nt);

    // ---- flush positives (2x by symmetry) ----
    if (J == I + 64 && diagWarp) {
        float pw = pv;
        #pragma unroll
        for (int o = 16; o >= 1; o >>= 1)
            pw += __shfl_xor_sync(0xffffffffu, pw, o);
        if (lane == 0) atomicAdd(&g_pos, 2.0 * (double)pw);
    }

    // ---- reduce rows across the 4 lanes sharing q, flush ----
    #pragma unroll
    for (int mt = 0; mt < 4; mt++) {
        #pragma unroll
        for (int o = 1; o <= 2; o <<= 1) {
            rsl[mt] += __shfl_xor_sync(0xffffffffu, rsl[mt], o);
            rsh[mt] += __shfl_xor_sync(0xffffffffu, rsh[mt], o);
        }
    }
    if ((lane & 3) == 0) {
        #pragma unroll
        for (int mt = 0; mt < 4; mt++) {
            int r = I * 128 + mw * 64 + mt * 16 + q;
            atomicAdd(&g_lrow[r], rsl[mt]);
            atomicAdd(&g_lrow[r + 8], rsh[mt]);
        }
    }

    __syncthreads();
    if (doCols)
        atomicAdd(&g_lrow[J * 128 + tid], colsum[tid]);
}

// -------------------------------------------------------------------- fin
__global__ void ntxent_fin1() {
    int r = blockIdx.x * 256 + threadIdx.x;
    float v = M0F + log2f(g_lrow[r]);
    #pragma unroll
    for (int o = 16; o >= 1; o >>= 1)
        v += __shfl_xor_sync(0xffffffffu, v, o);
    if ((threadIdx.x & 31) == 0) atomicAdd(&g_acc, (double)v);
}

__global__ void ntxent_fin2(float* out) {
    out[0] = (float)((g_acc - g_pos) * 0.6931471805599453 / (double)NTOT);
}

// ---------------------------------------------------------------------------
extern "C" void kernel_launch(void* const* d_in, const int* in_sizes, int n_in,
                              void* d_out, int out_size) {
    const float* zi = (const float*)d_in[0];
    const float* zj = (const float*)d_in[1];
    float* out = (float*)d_out;

    cudaFuncSetAttribute(ntxent_main,
                         cudaFuncAttributeMaxDynamicSharedMemorySize, 66048);

    ntxent_prep<<<(NTOT * 64) / 256, 256>>>(zi, zj);
    ntxent_main<<<NPAIR, 128, 66048>>>();
    ntxent_fin1<<<NTOT / 256, 256>>>();
    ntxent_fin2<<<1, 1>>>(out);
}